// round 1
// baseline (speedup 1.0000x reference)
#include <cuda_runtime.h>

#define B_  8
#define S_  1024
#define H_  1024
#define NH  16
#define HD  64
#define M_  (B_ * S_)   // 8192

// Scratch for Q/K/V in [B, nH, S, d] layout (allocation-free rule: __device__ globals)
__device__ float g_q[B_ * NH * S_ * HD];
__device__ float g_k[B_ * NH * S_ * HD];
__device__ float g_v[B_ * NH * S_ * HD];

// ---------------------------------------------------------------------------
// QKV projection: Y = X @ W^T + b   (X: [8192,1024] row-major, W: [1024,1024]
// row-major over [out,in] -> both operands are K-major, classic "NT" GEMM).
// BM=BN=128, BK=16, 256 threads, 8x8 microtile. blockIdx.z selects q/k/v.
// Output written directly into [B, nH, S, d] layout.
// ---------------------------------------------------------------------------
__global__ __launch_bounds__(256) void qkv_gemm_kernel(
    const float* __restrict__ X,
    const float* __restrict__ Wq, const float* __restrict__ Bq,
    const float* __restrict__ Wk, const float* __restrict__ Bk,
    const float* __restrict__ Wv, const float* __restrict__ Bv)
{
    const int which = blockIdx.z;
    const float* W    = (which == 0) ? Wq : (which == 1 ? Wk : Wv);
    const float* bias = (which == 0) ? Bq : (which == 1 ? Bk : Bv);
    float* out        = (which == 0) ? g_q : (which == 1 ? g_k : g_v);

    __shared__ __align__(16) float sA[16][132];   // [k][m], padded
    __shared__ __align__(16) float sB[16][132];   // [k][n], padded

    const int tid = threadIdx.x;
    const int tx  = tid & 15;
    const int ty  = tid >> 4;
    const int m0  = blockIdx.y * 128;
    const int n0  = blockIdx.x * 128;

    const int lr = tid >> 2;         // 0..63
    const int lc = (tid & 3) << 2;   // 0,4,8,12

    float acc[8][8];
    #pragma unroll
    for (int i = 0; i < 8; i++)
        #pragma unroll
        for (int j = 0; j < 8; j++) acc[i][j] = 0.0f;

    const float* ax0 = X + (size_t)(m0 + lr)      * H_ + lc;
    const float* ax1 = X + (size_t)(m0 + lr + 64) * H_ + lc;
    const float* bx0 = W + (size_t)(n0 + lr)      * H_ + lc;
    const float* bx1 = W + (size_t)(n0 + lr + 64) * H_ + lc;

    for (int k0 = 0; k0 < H_; k0 += 16) {
        float4 a0 = *(const float4*)(ax0 + k0);
        float4 a1 = *(const float4*)(ax1 + k0);
        float4 b0 = *(const float4*)(bx0 + k0);
        float4 b1 = *(const float4*)(bx1 + k0);

        sA[lc+0][lr]    = a0.x; sA[lc+1][lr]    = a0.y; sA[lc+2][lr]    = a0.z; sA[lc+3][lr]    = a0.w;
        sA[lc+0][lr+64] = a1.x; sA[lc+1][lr+64] = a1.y; sA[lc+2][lr+64] = a1.z; sA[lc+3][lr+64] = a1.w;
        sB[lc+0][lr]    = b0.x; sB[lc+1][lr]    = b0.y; sB[lc+2][lr]    = b0.z; sB[lc+3][lr]    = b0.w;
        sB[lc+0][lr+64] = b1.x; sB[lc+1][lr+64] = b1.y; sB[lc+2][lr+64] = b1.z; sB[lc+3][lr+64] = b1.w;
        __syncthreads();

        #pragma unroll
        for (int kk = 0; kk < 16; kk++) {
            float4 af0 = *(const float4*)&sA[kk][ty * 8];
            float4 af1 = *(const float4*)&sA[kk][ty * 8 + 4];
            float4 bf0 = *(const float4*)&sB[kk][tx * 8];
            float4 bf1 = *(const float4*)&sB[kk][tx * 8 + 4];
            float a_[8] = {af0.x, af0.y, af0.z, af0.w, af1.x, af1.y, af1.z, af1.w};
            float b_[8] = {bf0.x, bf0.y, bf0.z, bf0.w, bf1.x, bf1.y, bf1.z, bf1.w};
            #pragma unroll
            for (int i = 0; i < 8; i++)
                #pragma unroll
                for (int j = 0; j < 8; j++)
                    acc[i][j] = fmaf(a_[i], b_[j], acc[i][j]);
        }
        __syncthreads();
    }

    // epilogue: +bias, scatter into [B, nH, S, d]
    float bv[8];
    #pragma unroll
    for (int j = 0; j < 8; j++) bv[j] = bias[n0 + tx * 8 + j];

    #pragma unroll
    for (int i = 0; i < 8; i++) {
        const int m = m0 + ty * 8 + i;
        const int b = m >> 10;
        const int s = m & 1023;
        #pragma unroll
        for (int jj = 0; jj < 8; jj += 4) {
            const int n  = n0 + tx * 8 + jj;
            const int h  = n >> 6;
            const int dd = n & 63;
            float4 v;
            v.x = acc[i][jj + 0] + bv[jj + 0];
            v.y = acc[i][jj + 1] + bv[jj + 1];
            v.z = acc[i][jj + 2] + bv[jj + 2];
            v.w = acc[i][jj + 3] + bv[jj + 3];
            *(float4*)&out[(((size_t)(b * NH + h) * S_) + s) * HD + dd] = v;
        }
    }
}

// ---------------------------------------------------------------------------
// Flash attention, fp32, online softmax. One block per (bh, 64-query tile).
// 256 threads, 16x16 grid, 4x4 microtiles over 64x64 score/context tiles.
// SMEM: Q^T (d-major), K^T (d-major, buffer reused for P^T), V (k-major).
// 3 * 16 KB = 48 KB static shared (at the limit, no attribute call needed).
// ---------------------------------------------------------------------------
__global__ __launch_bounds__(256) void attn_kernel(float* __restrict__ out)
{
    __shared__ __align__(16) float sQt[64 * 64];   // [d][q]
    __shared__ __align__(16) float sKPt[64 * 64];  // [d][k] then reused as [k][q]
    __shared__ __align__(16) float sV[64 * 64];    // [k][d]

    const int tid = threadIdx.x;
    const int tx  = tid & 15;
    const int ty  = tid >> 4;
    const int bh  = blockIdx.y;   // 0..127
    const int qt  = blockIdx.x;   // 0..15

    const float* Q = g_q + (size_t)bh * S_ * HD + (size_t)qt * 64 * HD;
    const float* K = g_k + (size_t)bh * S_ * HD;
    const float* V = g_v + (size_t)bh * S_ * HD;

    // Load Q tile transposed, pre-scaled by 1/sqrt(64) = 0.125
    {
        const int r  = tid >> 2;
        const int c0 = (tid & 3) << 2;
        #pragma unroll
        for (int it = 0; it < 4; it++) {
            const int c = c0 + it * 16;
            float4 v = *(const float4*)&Q[r * HD + c];
            sQt[(c + 0) * 64 + r] = v.x * 0.125f;
            sQt[(c + 1) * 64 + r] = v.y * 0.125f;
            sQt[(c + 2) * 64 + r] = v.z * 0.125f;
            sQt[(c + 3) * 64 + r] = v.w * 0.125f;
        }
    }

    float o[4][4];
    #pragma unroll
    for (int i = 0; i < 4; i++)
        #pragma unroll
        for (int j = 0; j < 4; j++) o[i][j] = 0.0f;
    float mst[4] = {-1e30f, -1e30f, -1e30f, -1e30f};
    float lst[4] = {0.0f, 0.0f, 0.0f, 0.0f};

    for (int t = 0; t < 16; t++) {
        __syncthreads();  // previous iteration done with sKPt (as P) and sV

        // Load K tile transposed + V tile direct
        {
            const int r  = tid >> 2;
            const int c0 = (tid & 3) << 2;
            const float* Kt = K + (size_t)t * 64 * HD;
            #pragma unroll
            for (int it = 0; it < 4; it++) {
                const int c = c0 + it * 16;
                float4 v = *(const float4*)&Kt[r * HD + c];
                sKPt[(c + 0) * 64 + r] = v.x;
                sKPt[(c + 1) * 64 + r] = v.y;
                sKPt[(c + 2) * 64 + r] = v.z;
                sKPt[(c + 3) * 64 + r] = v.w;
            }
            const float4* Vg = (const float4*)(V + (size_t)t * 64 * HD);
            float4* Vs = (float4*)sV;
            #pragma unroll
            for (int it = 0; it < 4; it++) Vs[tid + it * 256] = Vg[tid + it * 256];
        }
        __syncthreads();

        // S = (Q * scale) @ K^T  (contraction over d=64)
        float s[4][4];
        #pragma unroll
        for (int i = 0; i < 4; i++)
            #pragma unroll
            for (int j = 0; j < 4; j++) s[i][j] = 0.0f;

        #pragma unroll 16
        for (int d = 0; d < 64; d++) {
            float4 q4 = *(const float4*)&sQt[d * 64 + ty * 4];
            float4 k4 = *(const float4*)&sKPt[d * 64 + tx * 4];
            float qa[4] = {q4.x, q4.y, q4.z, q4.w};
            float ka[4] = {k4.x, k4.y, k4.z, k4.w};
            #pragma unroll
            for (int i = 0; i < 4; i++)
                #pragma unroll
                for (int j = 0; j < 4; j++)
                    s[i][j] = fmaf(qa[i], ka[j], s[i][j]);
        }

        // Online softmax. Row groups = 16 lanes (same half-warp): xor 1,2,4,8.
        #pragma unroll
        for (int i = 0; i < 4; i++) {
            float rm = fmaxf(fmaxf(s[i][0], s[i][1]), fmaxf(s[i][2], s[i][3]));
            rm = fmaxf(rm, __shfl_xor_sync(0xffffffffu, rm, 1));
            rm = fmaxf(rm, __shfl_xor_sync(0xffffffffu, rm, 2));
            rm = fmaxf(rm, __shfl_xor_sync(0xffffffffu, rm, 4));
            rm = fmaxf(rm, __shfl_xor_sync(0xffffffffu, rm, 8));
            const float mn   = fmaxf(mst[i], rm);
            const float corr = __expf(mst[i] - mn);
            mst[i] = mn;
            float rs = 0.0f;
            #pragma unroll
            for (int j = 0; j < 4; j++) {
                s[i][j] = __expf(s[i][j] - mn);
                rs += s[i][j];
            }
            rs += __shfl_xor_sync(0xffffffffu, rs, 1);
            rs += __shfl_xor_sync(0xffffffffu, rs, 2);
            rs += __shfl_xor_sync(0xffffffffu, rs, 4);
            rs += __shfl_xor_sync(0xffffffffu, rs, 8);
            lst[i] = lst[i] * corr + rs;
            #pragma unroll
            for (int j = 0; j < 4; j++) o[i][j] *= corr;
        }

        __syncthreads();  // all threads done reading sKPt as K^T
        // Store P^T into the K buffer: [k][q]
        #pragma unroll
        for (int i = 0; i < 4; i++)
            #pragma unroll
            for (int j = 0; j < 4; j++)
                sKPt[(tx * 4 + j) * 64 + (ty * 4 + i)] = s[i][j];
        __syncthreads();

        // O += P @ V  (contraction over k=64)
        #pragma unroll 16
        for (int k = 0; k < 64; k++) {
            float4 p4 = *(const float4*)&sKPt[k * 64 + ty * 4];
            float4 v4 = *(const float4*)&sV[k * 64 + tx * 4];
            float pa[4] = {p4.x, p4.y, p4.z, p4.w};
            float va[4] = {v4.x, v4.y, v4.z, v4.w};
            #pragma unroll
            for (int i = 0; i < 4; i++)
                #pragma unroll
                for (int j = 0; j < 4; j++)
                    o[i][j] = fmaf(pa[i], va[j], o[i][j]);
        }
    }

    // Epilogue: normalize, write [B, S, H]
    const int b = bh >> 4;
    const int h = bh & 15;
    #pragma unroll
    for (int i = 0; i < 4; i++) {
        const float inv = 1.0f / lst[i];
        const int s_g = qt * 64 + ty * 4 + i;
        float4 v;
        v.x = o[i][0] * inv;
        v.y = o[i][1] * inv;
        v.z = o[i][2] * inv;
        v.w = o[i][3] * inv;
        *(float4*)&out[((size_t)(b * S_ + s_g)) * H_ + h * HD + tx * 4] = v;
    }
}

extern "C" void kernel_launch(void* const* d_in, const int* in_sizes, int n_in,
                              void* d_out, int out_size)
{
    const float* X  = (const float*)d_in[0];
    const float* Wq = (const float*)d_in[1];
    const float* Bq = (const float*)d_in[2];
    const float* Wk = (const float*)d_in[3];
    const float* Bk = (const float*)d_in[4];
    const float* Wv = (const float*)d_in[5];
    const float* Bv = (const float*)d_in[6];
    float* out = (float*)d_out;

    dim3 g1(H_ / 128, M_ / 128, 3);   // (8, 64, 3)
    qkv_gemm_kernel<<<g1, 256>>>(X, Wq, Bq, Wk, Bk, Wv, Bv);

    dim3 g2(S_ / 64, B_ * NH);        // (16, 128)
    attn_kernel<<<g2, 256>>>(out);
}

// round 4
// speedup vs baseline: 2.3333x; 2.3333x over previous
#include <cuda_runtime.h>
#include <cstdint>

#define B_  8
#define S_  1024
#define H_  1024
#define NH  16
#define HD  64
#define M_  (B_ * S_)   // 8192

// Q/K/V scratch in [B, nH, S, d] layout
__device__ float g_q[B_ * NH * S_ * HD];
__device__ float g_k[B_ * NH * S_ * HD];
__device__ float g_v[B_ * NH * S_ * HD];

__device__ __forceinline__ uint32_t f2tf(float x) {
    uint32_t r;
    asm("cvt.rna.tf32.f32 %0, %1;" : "=r"(r) : "f"(x));
    return r;
}

__device__ __forceinline__ void mma_tf32(float c[4],
                                         uint32_t a0, uint32_t a1, uint32_t a2, uint32_t a3,
                                         uint32_t b0, uint32_t b1) {
    asm volatile(
        "mma.sync.aligned.m16n8k8.row.col.f32.tf32.tf32.f32 "
        "{%0,%1,%2,%3}, {%4,%5,%6,%7}, {%8,%9}, {%0,%1,%2,%3};\n"
        : "+f"(c[0]), "+f"(c[1]), "+f"(c[2]), "+f"(c[3])
        : "r"(a0), "r"(a1), "r"(a2), "r"(a3), "r"(b0), "r"(b1));
}

// ---------------------------------------------------------------------------
// TF32 QKV GEMM: Y = X @ W^T + b.  BM=BN=128, BK=16, double-buffered.
// 8 warps as 4x2 -> warp tile 32x64. Pad-20 smem rows: conflict-free frags.
// ---------------------------------------------------------------------------
#define GP 20   // padded row length (16 k + 4)

__global__ __launch_bounds__(256) void qkv_gemm_tf32(
    const float* __restrict__ X,
    const float* __restrict__ Wq, const float* __restrict__ Bq,
    const float* __restrict__ Wk, const float* __restrict__ Bk,
    const float* __restrict__ Wv, const float* __restrict__ Bv)
{
    const int which = blockIdx.z;
    const float* W    = (which == 0) ? Wq : (which == 1 ? Wk : Wv);
    const float* bias = (which == 0) ? Bq : (which == 1 ? Bk : Bv);
    float* out        = (which == 0) ? g_q : (which == 1 ? g_k : g_v);

    __shared__ uint32_t sA[2][128 * GP];
    __shared__ uint32_t sB[2][128 * GP];

    const int tid  = threadIdx.x;
    const int lane = tid & 31;
    const int wid  = tid >> 5;
    const int wm   = (wid >> 1) * 32;   // warp m offset (0,32,64,96)
    const int wn   = (wid & 1) * 64;    // warp n offset (0,64)
    const int m0   = blockIdx.y * 128;
    const int n0   = blockIdx.x * 128;

    const int lrow = tid >> 1;          // 0..127
    const int lcol = (tid & 1) * 8;     // 0 or 8

    const float* pA = X + (size_t)(m0 + lrow) * H_ + lcol;
    const float* pB = W + (size_t)(n0 + lrow) * H_ + lcol;
    uint32_t* stA = &sA[0][0] + lrow * GP + lcol;   // buffer 0 base; +128*GP for buf1
    uint32_t* stB = &sB[0][0] + lrow * GP + lcol;

    float c[2][8][4];
    #pragma unroll
    for (int i = 0; i < 2; i++)
        #pragma unroll
        for (int j = 0; j < 8; j++)
            #pragma unroll
            for (int k = 0; k < 4; k++) c[i][j][k] = 0.0f;

    // prologue: tile 0
    float4 a0_ = *(const float4*)(pA);
    float4 a1_ = *(const float4*)(pA + 4);
    float4 b0_ = *(const float4*)(pB);
    float4 b1_ = *(const float4*)(pB + 4);
    {
        uint4 ua0 = {f2tf(a0_.x), f2tf(a0_.y), f2tf(a0_.z), f2tf(a0_.w)};
        uint4 ua1 = {f2tf(a1_.x), f2tf(a1_.y), f2tf(a1_.z), f2tf(a1_.w)};
        uint4 ub0 = {f2tf(b0_.x), f2tf(b0_.y), f2tf(b0_.z), f2tf(b0_.w)};
        uint4 ub1 = {f2tf(b1_.x), f2tf(b1_.y), f2tf(b1_.z), f2tf(b1_.w)};
        *(uint4*)(stA)     = ua0;
        *(uint4*)(stA + 4) = ua1;
        *(uint4*)(stB)     = ub0;
        *(uint4*)(stB + 4) = ub1;
    }
    __syncthreads();

    const int NT = H_ / 16;   // 64
    for (int t = 0; t < NT; t++) {
        const int cur = t & 1;
        if (t + 1 < NT) {
            const float* nA = pA + (t + 1) * 16;
            const float* nB = pB + (t + 1) * 16;
            a0_ = *(const float4*)(nA);
            a1_ = *(const float4*)(nA + 4);
            b0_ = *(const float4*)(nB);
            b1_ = *(const float4*)(nB + 4);
        }

        const uint32_t* cA = &sA[cur][0];
        const uint32_t* cB = &sB[cur][0];
        #pragma unroll
        for (int kk = 0; kk < 16; kk += 8) {
            uint32_t af[2][4];
            #pragma unroll
            for (int mi = 0; mi < 2; mi++) {
                const int r = wm + mi * 16 + (lane >> 2);
                af[mi][0] = cA[r * GP + kk + (lane & 3)];
                af[mi][1] = cA[(r + 8) * GP + kk + (lane & 3)];
                af[mi][2] = cA[r * GP + kk + 4 + (lane & 3)];
                af[mi][3] = cA[(r + 8) * GP + kk + 4 + (lane & 3)];
            }
            uint32_t bf[8][2];
            #pragma unroll
            for (int ni = 0; ni < 8; ni++) {
                const int n = wn + ni * 8 + (lane >> 2);
                bf[ni][0] = cB[n * GP + kk + (lane & 3)];
                bf[ni][1] = cB[n * GP + kk + 4 + (lane & 3)];
            }
            #pragma unroll
            for (int mi = 0; mi < 2; mi++)
                #pragma unroll
                for (int ni = 0; ni < 8; ni++)
                    mma_tf32(c[mi][ni], af[mi][0], af[mi][1], af[mi][2], af[mi][3],
                             bf[ni][0], bf[ni][1]);
        }

        if (t + 1 < NT) {
            uint32_t* dA = stA + ((t + 1) & 1) * 128 * GP;
            uint32_t* dB = stB + ((t + 1) & 1) * 128 * GP;
            uint4 ua0 = {f2tf(a0_.x), f2tf(a0_.y), f2tf(a0_.z), f2tf(a0_.w)};
            uint4 ua1 = {f2tf(a1_.x), f2tf(a1_.y), f2tf(a1_.z), f2tf(a1_.w)};
            uint4 ub0 = {f2tf(b0_.x), f2tf(b0_.y), f2tf(b0_.z), f2tf(b0_.w)};
            uint4 ub1 = {f2tf(b1_.x), f2tf(b1_.y), f2tf(b1_.z), f2tf(b1_.w)};
            *(uint4*)(dA)     = ua0;
            *(uint4*)(dA + 4) = ua1;
            *(uint4*)(dB)     = ub0;
            *(uint4*)(dB + 4) = ub1;
        }
        __syncthreads();
    }

    // epilogue: +bias, scatter to [B, nH, S, d]
    #pragma unroll
    for (int mi = 0; mi < 2; mi++) {
        #pragma unroll
        for (int rh = 0; rh < 2; rh++) {
            const int m = m0 + wm + mi * 16 + (lane >> 2) + rh * 8;
            const int b = m >> 10;
            const int s = m & 1023;
            float* orow = out + ((size_t)(b * NH) * S_ + s) * HD;  // + h*S_*HD later
            #pragma unroll
            for (int ni = 0; ni < 8; ni++) {
                const int n = n0 + wn + ni * 8 + (lane & 3) * 2;
                const int h = n >> 6;
                const int dd = n & 63;
                float2 v;
                v.x = c[mi][ni][rh * 2 + 0] + bias[n];
                v.y = c[mi][ni][rh * 2 + 1] + bias[n + 1];
                *(float2*)(orow + (size_t)h * S_ * HD + dd) = v;
            }
        }
    }
}

// ---------------------------------------------------------------------------
// TF32 flash attention. Block = 256 thr (8 warps), q-tile = 128 rows, one bh.
// Warp w owns q rows [w*16, w*16+16) -> softmax stats warp-local.
// kv tiles of 64. S = Q@K^T, P->smem(tf32), O += P@V.
// smem (dynamic, pad 68): sQ[128], sK[64], sVt[64], sP[128] rows.
// ---------------------------------------------------------------------------
#define AP 68

__global__ __launch_bounds__(256) void attn_tf32(float* __restrict__ out)
{
    extern __shared__ uint32_t sm[];
    uint32_t* sQ  = sm;                       // [128][AP] (q, d) tf32, pre-scaled
    uint32_t* sK  = sQ + 128 * AP;            // [64][AP]  (kv, d) tf32
    uint32_t* sVt = sK + 64 * AP;             // [64][AP]  (d, kv) tf32
    uint32_t* sP  = sVt + 64 * AP;            // [128][AP] (q, kv) tf32

    const int tid  = threadIdx.x;
    const int lane = tid & 31;
    const int wid  = tid >> 5;
    const int wq   = wid * 16;                // warp's q-row base within tile
    const int bh   = blockIdx.y;              // 0..127
    const int qt   = blockIdx.x;              // 0..7 (128-row tiles)

    const float* Q = g_q + (size_t)bh * S_ * HD + (size_t)qt * 128 * HD;
    const float* K = g_k + (size_t)bh * S_ * HD;
    const float* V = g_v + (size_t)bh * S_ * HD;

    // Load Q tile (128x64), scale by 0.125, cvt tf32
    {
        const int r  = tid >> 1;              // 0..127
        const int c0 = (tid & 1) * 32;
        #pragma unroll
        for (int j = 0; j < 8; j++) {
            const int cc = c0 + j * 4;
            float4 v = *(const float4*)&Q[r * HD + cc];
            uint4 u = {f2tf(v.x * 0.125f), f2tf(v.y * 0.125f),
                       f2tf(v.z * 0.125f), f2tf(v.w * 0.125f)};
            *(uint4*)&sQ[r * AP + cc] = u;
        }
    }

    float o[8][4];
    #pragma unroll
    for (int i = 0; i < 8; i++)
        #pragma unroll
        for (int j = 0; j < 4; j++) o[i][j] = 0.0f;
    float mr0 = -1e30f, mr1 = -1e30f;   // row stats: rows lane>>2, +8
    float lr0 = 0.0f,   lr1 = 0.0f;

    for (int t = 0; t < 16; t++) {
        __syncthreads();   // prev iter done with sK/sVt; sQ store visible at t=0

        // Load K tile (64x64) row-major + V tile transposed
        {
            const int r  = tid >> 2;          // 0..63
            const int c0 = (tid & 3) * 16;
            const float* Kt = K + (size_t)t * 64 * HD;
            const float* Vt = V + (size_t)t * 64 * HD;
            #pragma unroll
            for (int j = 0; j < 4; j++) {
                const int cc = c0 + j * 4;
                float4 kv4 = *(const float4*)&Kt[r * HD + cc];
                uint4 uk = {f2tf(kv4.x), f2tf(kv4.y), f2tf(kv4.z), f2tf(kv4.w)};
                *(uint4*)&sK[r * AP + cc] = uk;
                float4 vv4 = *(const float4*)&Vt[r * HD + cc];
                sVt[(cc + 0) * AP + r] = f2tf(vv4.x);
                sVt[(cc + 1) * AP + r] = f2tf(vv4.y);
                sVt[(cc + 2) * AP + r] = f2tf(vv4.z);
                sVt[(cc + 3) * AP + r] = f2tf(vv4.w);
            }
        }
        __syncthreads();

        // S = Q @ K^T over d=64 (8 k-steps), warp covers q16 x kv64 (8 n-tiles)
        float s[8][4];
        #pragma unroll
        for (int i = 0; i < 8; i++)
            #pragma unroll
            for (int j = 0; j < 4; j++) s[i][j] = 0.0f;

        #pragma unroll
        for (int kk = 0; kk < 64; kk += 8) {
            const int r = wq + (lane >> 2);
            uint32_t a0 = sQ[r * AP + kk + (lane & 3)];
            uint32_t a1 = sQ[(r + 8) * AP + kk + (lane & 3)];
            uint32_t a2 = sQ[r * AP + kk + 4 + (lane & 3)];
            uint32_t a3 = sQ[(r + 8) * AP + kk + 4 + (lane & 3)];
            #pragma unroll
            for (int ni = 0; ni < 8; ni++) {
                const int n = ni * 8 + (lane >> 2);
                uint32_t b0 = sK[n * AP + kk + (lane & 3)];
                uint32_t b1 = sK[n * AP + kk + 4 + (lane & 3)];
                mma_tf32(s[ni], a0, a1, a2, a3, b0, b1);
            }
        }

        // Online softmax (rows lane>>2 and lane>>2 + 8; reduce over lane&3)
        {
            float rm0 = -1e30f, rm1 = -1e30f;
            #pragma unroll
            for (int ni = 0; ni < 8; ni++) {
                rm0 = fmaxf(rm0, fmaxf(s[ni][0], s[ni][1]));
                rm1 = fmaxf(rm1, fmaxf(s[ni][2], s[ni][3]));
            }
            rm0 = fmaxf(rm0, __shfl_xor_sync(0xffffffffu, rm0, 1));
            rm0 = fmaxf(rm0, __shfl_xor_sync(0xffffffffu, rm0, 2));
            rm1 = fmaxf(rm1, __shfl_xor_sync(0xffffffffu, rm1, 1));
            rm1 = fmaxf(rm1, __shfl_xor_sync(0xffffffffu, rm1, 2));

            const float mn0 = fmaxf(mr0, rm0);
            const float mn1 = fmaxf(mr1, rm1);
            const float cor0 = __expf(mr0 - mn0);
            const float cor1 = __expf(mr1 - mn1);
            mr0 = mn0; mr1 = mn1;

            float rs0 = 0.0f, rs1 = 0.0f;
            #pragma unroll
            for (int ni = 0; ni < 8; ni++) {
                s[ni][0] = __expf(s[ni][0] - mn0);
                s[ni][1] = __expf(s[ni][1] - mn0);
                s[ni][2] = __expf(s[ni][2] - mn1);
                s[ni][3] = __expf(s[ni][3] - mn1);
                rs0 += s[ni][0] + s[ni][1];
                rs1 += s[ni][2] + s[ni][3];
            }
            rs0 += __shfl_xor_sync(0xffffffffu, rs0, 1);
            rs0 += __shfl_xor_sync(0xffffffffu, rs0, 2);
            rs1 += __shfl_xor_sync(0xffffffffu, rs1, 1);
            rs1 += __shfl_xor_sync(0xffffffffu, rs1, 2);
            lr0 = lr0 * cor0 + rs0;
            lr1 = lr1 * cor1 + rs1;

            #pragma unroll
            for (int ni = 0; ni < 8; ni++) {
                o[ni][0] *= cor0; o[ni][1] *= cor0;
                o[ni][2] *= cor1; o[ni][3] *= cor1;
            }
        }

        // Write P (tf32) to sP — warp-private rows, syncwarp suffices
        #pragma unroll
        for (int ni = 0; ni < 8; ni++) {
            const int cc = ni * 8 + (lane & 3) * 2;
            const int r0 = wq + (lane >> 2);
            uint2 u0 = {f2tf(s[ni][0]), f2tf(s[ni][1])};
            uint2 u1 = {f2tf(s[ni][2]), f2tf(s[ni][3])};
            *(uint2*)&sP[r0 * AP + cc]       = u0;
            *(uint2*)&sP[(r0 + 8) * AP + cc] = u1;
        }
        __syncwarp();

        // O += P @ V over kv=64 (8 k-steps), warp covers q16 x d64
        #pragma unroll
        for (int kk = 0; kk < 64; kk += 8) {
            const int r = wq + (lane >> 2);
            uint32_t a0 = sP[r * AP + kk + (lane & 3)];
            uint32_t a1 = sP[(r + 8) * AP + kk + (lane & 3)];
            uint32_t a2 = sP[r * AP + kk + 4 + (lane & 3)];
            uint32_t a3 = sP[(r + 8) * AP + kk + 4 + (lane & 3)];
            #pragma unroll
            for (int ni = 0; ni < 8; ni++) {
                const int n = ni * 8 + (lane >> 2);   // d index
                uint32_t b0 = sVt[n * AP + kk + (lane & 3)];
                uint32_t b1 = sVt[n * AP + kk + 4 + (lane & 3)];
                mma_tf32(o[ni], a0, a1, a2, a3, b0, b1);
            }
        }
    }

    // Epilogue: normalize, write [B, S, H]
    const int b = bh >> 4;
    const int h = bh & 15;
    const float inv0 = 1.0f / lr0;
    const float inv1 = 1.0f / lr1;
    const int s0 = qt * 128 + wq + (lane >> 2);
    float* out0 = out + ((size_t)(b * S_ + s0)) * H_ + h * HD;
    float* out1 = out + ((size_t)(b * S_ + s0 + 8)) * H_ + h * HD;
    #pragma unroll
    for (int ni = 0; ni < 8; ni++) {
        const int dd = ni * 8 + (lane & 3) * 2;
        float2 v0 = {o[ni][0] * inv0, o[ni][1] * inv0};
        float2 v1 = {o[ni][2] * inv1, o[ni][3] * inv1};
        *(float2*)(out0 + dd) = v0;
        *(float2*)(out1 + dd) = v1;
    }
}

extern "C" void kernel_launch(void* const* d_in, const int* in_sizes, int n_in,
                              void* d_out, int out_size)
{
    const float* X  = (const float*)d_in[0];
    const float* Wq = (const float*)d_in[1];
    const float* Bq = (const float*)d_in[2];
    const float* Wk = (const float*)d_in[3];
    const float* Bk = (const float*)d_in[4];
    const float* Wv = (const float*)d_in[5];
    const float* Bv = (const float*)d_in[6];
    float* out = (float*)d_out;

    dim3 g1(H_ / 128, M_ / 128, 3);     // (8, 64, 3)
    qkv_gemm_tf32<<<g1, 256>>>(X, Wq, Bq, Wk, Bk, Wv, Bv);

    const int smem_attn = (128 + 64 + 64 + 128) * AP * 4;   // 104448 B
    cudaFuncSetAttribute(attn_tf32, cudaFuncAttributeMaxDynamicSharedMemorySize, smem_attn);
    dim3 g2(S_ / 128, B_ * NH);         // (8, 128)
    attn_tf32<<<g2, 256, smem_attn>>>(out);
}

// round 8
// speedup vs baseline: 2.6250x; 1.1250x over previous
#include <cuda_runtime.h>
#include <cstdint>

#define B_  8
#define S_  1024
#define H_  1024
#define NH  16
#define HD  64
#define M_  (B_ * S_)   // 8192

__device__ float g_q[B_ * NH * S_ * HD];
__device__ float g_k[B_ * NH * S_ * HD];
__device__ float g_v[B_ * NH * S_ * HD];

__device__ __forceinline__ uint32_t f2tf(float x) {
    uint32_t r;
    asm("cvt.rna.tf32.f32 %0, %1;" : "=r"(r) : "f"(x));
    return r;
}

__device__ __forceinline__ void mma_tf32(float c[4],
                                         uint32_t a0, uint32_t a1, uint32_t a2, uint32_t a3,
                                         uint32_t b0, uint32_t b1) {
    asm volatile(
        "mma.sync.aligned.m16n8k8.row.col.f32.tf32.tf32.f32 "
        "{%0,%1,%2,%3}, {%4,%5,%6,%7}, {%8,%9}, {%0,%1,%2,%3};\n"
        : "+f"(c[0]), "+f"(c[1]), "+f"(c[2]), "+f"(c[3])
        : "r"(a0), "r"(a1), "r"(a2), "r"(a3), "r"(b0), "r"(b1));
}

// ---------------------------------------------------------------------------
// TF32 QKV GEMM, k-pair interleaved smem: within each 8-k group, element k
// sits at (k&3)*2 + (k>>2), so fragment words (k, k+4) are one LDS.64.
// BM=BN=128, BK=16, double-buffered. 8 warps 4x2, warp tile 32x64.
// ---------------------------------------------------------------------------
#define GP 24   // padded row (16 k + 8); r*24 mod 32 conflict-free per half-warp

__global__ __launch_bounds__(256) void qkv_gemm_tf32(
    const float* __restrict__ X,
    const float* __restrict__ Wq, const float* __restrict__ Bq,
    const float* __restrict__ Wk, const float* __restrict__ Bk,
    const float* __restrict__ Wv, const float* __restrict__ Bv)
{
    const int which = blockIdx.z;
    const float* W    = (which == 0) ? Wq : (which == 1 ? Wk : Wv);
    const float* bias = (which == 0) ? Bq : (which == 1 ? Bk : Bv);
    float* out        = (which == 0) ? g_q : (which == 1 ? g_k : g_v);

    __shared__ uint32_t sA[2][128 * GP];
    __shared__ uint32_t sB[2][128 * GP];

    const int tid  = threadIdx.x;
    const int lane = tid & 31;
    const int wid  = tid >> 5;
    const int wm   = (wid >> 1) * 32;
    const int wn   = (wid & 1) * 64;
    const int m0   = blockIdx.y * 128;
    const int n0   = blockIdx.x * 128;
    const int r8   = lane >> 2;
    const int la3  = lane & 3;

    const int lrow = tid >> 1;          // 0..127
    const int lcol = (tid & 1) * 8;     // group base: 0 or 8

    const float* pA = X + (size_t)(m0 + lrow) * H_ + lcol;
    const float* pB = W + (size_t)(n0 + lrow) * H_ + lcol;
    uint32_t* stA = &sA[0][0] + lrow * GP + lcol;
    uint32_t* stB = &sB[0][0] + lrow * GP + lcol;

    float c[2][8][4];
    #pragma unroll
    for (int i = 0; i < 2; i++)
        #pragma unroll
        for (int j = 0; j < 8; j++)
            #pragma unroll
            for (int k = 0; k < 4; k++) c[i][j][k] = 0.0f;

    // prologue: tile 0 (lo = k 0..3 of group, hi = k 4..7 -> interleaved pairs)
    float4 alo = *(const float4*)(pA);
    float4 ahi = *(const float4*)(pA + 4);
    float4 blo = *(const float4*)(pB);
    float4 bhi = *(const float4*)(pB + 4);
    {
        *(uint2*)(stA + 0) = make_uint2(f2tf(alo.x), f2tf(ahi.x));
        *(uint2*)(stA + 2) = make_uint2(f2tf(alo.y), f2tf(ahi.y));
        *(uint2*)(stA + 4) = make_uint2(f2tf(alo.z), f2tf(ahi.z));
        *(uint2*)(stA + 6) = make_uint2(f2tf(alo.w), f2tf(ahi.w));
        *(uint2*)(stB + 0) = make_uint2(f2tf(blo.x), f2tf(bhi.x));
        *(uint2*)(stB + 2) = make_uint2(f2tf(blo.y), f2tf(bhi.y));
        *(uint2*)(stB + 4) = make_uint2(f2tf(blo.z), f2tf(bhi.z));
        *(uint2*)(stB + 6) = make_uint2(f2tf(blo.w), f2tf(bhi.w));
    }
    __syncthreads();

    const int NT = H_ / 16;   // 64
    for (int t = 0; t < NT; t++) {
        const int cur = t & 1;
        if (t + 1 < NT) {
            const float* nA = pA + (t + 1) * 16;
            const float* nB = pB + (t + 1) * 16;
            alo = *(const float4*)(nA);
            ahi = *(const float4*)(nA + 4);
            blo = *(const float4*)(nB);
            bhi = *(const float4*)(nB + 4);
        }

        const uint32_t* cA = &sA[cur][0];
        const uint32_t* cB = &sB[cur][0];
        #pragma unroll
        for (int g = 0; g < 2; g++) {
            uint2 uA0[2], uA1[2];
            #pragma unroll
            for (int mi = 0; mi < 2; mi++) {
                uA0[mi] = *(const uint2*)&cA[(wm + mi * 16 + r8) * GP + g * 8 + la3 * 2];
                uA1[mi] = *(const uint2*)&cA[(wm + mi * 16 + 8 + r8) * GP + g * 8 + la3 * 2];
            }
            #pragma unroll
            for (int ni = 0; ni < 8; ni++) {
                uint2 uB = *(const uint2*)&cB[(wn + ni * 8 + r8) * GP + g * 8 + la3 * 2];
                #pragma unroll
                for (int mi = 0; mi < 2; mi++)
                    mma_tf32(c[mi][ni], uA0[mi].x, uA1[mi].x, uA0[mi].y, uA1[mi].y,
                             uB.x, uB.y);
            }
        }

        if (t + 1 < NT) {
            uint32_t* dA = stA + ((t + 1) & 1) * 128 * GP;
            uint32_t* dB = stB + ((t + 1) & 1) * 128 * GP;
            *(uint2*)(dA + 0) = make_uint2(f2tf(alo.x), f2tf(ahi.x));
            *(uint2*)(dA + 2) = make_uint2(f2tf(alo.y), f2tf(ahi.y));
            *(uint2*)(dA + 4) = make_uint2(f2tf(alo.z), f2tf(ahi.z));
            *(uint2*)(dA + 6) = make_uint2(f2tf(alo.w), f2tf(ahi.w));
            *(uint2*)(dB + 0) = make_uint2(f2tf(blo.x), f2tf(bhi.x));
            *(uint2*)(dB + 2) = make_uint2(f2tf(blo.y), f2tf(bhi.y));
            *(uint2*)(dB + 4) = make_uint2(f2tf(blo.z), f2tf(bhi.z));
            *(uint2*)(dB + 6) = make_uint2(f2tf(blo.w), f2tf(bhi.w));
        }
        __syncthreads();
    }

    // epilogue: +bias, scatter to [B, nH, S, d]
    #pragma unroll
    for (int mi = 0; mi < 2; mi++) {
        #pragma unroll
        for (int rh = 0; rh < 2; rh++) {
            const int m = m0 + wm + mi * 16 + r8 + rh * 8;
            const int b = m >> 10;
            const int s = m & 1023;
            float* orow = out + ((size_t)(b * NH) * S_ + s) * HD;
            #pragma unroll
            for (int ni = 0; ni < 8; ni++) {
                const int n = n0 + wn + ni * 8 + la3 * 2;
                const int h = n >> 6;
                const int dd = n & 63;
                float2 v;
                v.x = c[mi][ni][rh * 2 + 0] + bias[n];
                v.y = c[mi][ni][rh * 2 + 1] + bias[n + 1];
                *(float2*)(orow + (size_t)h * S_ * HD + dd) = v;
            }
        }
    }
}

// ---------------------------------------------------------------------------
// TF32 flash attention. 256 thr, q-tile 128, warp w owns q rows [16w,16w+16).
// Q fragments hoisted into registers (loop-invariant); sQ buffer reused as sP.
// All smem in k-pair interleaved layout -> LDS.64 fragment loads.
// smem: sQP[128], sK[64], sVt[64] rows of AP=72 words = 73728 B.
// ---------------------------------------------------------------------------
#define AP 72

__global__ __launch_bounds__(256, 2) void attn_tf32(float* __restrict__ out)
{
    extern __shared__ uint32_t sm[];
    uint32_t* sQP = sm;                       // Q staging, then P  [128][AP]
    uint32_t* sK  = sQP + 128 * AP;           // [64][AP] (kv, d-interleaved)
    uint32_t* sVt = sK + 64 * AP;             // [64][AP] (d, kv-interleaved)

    const int tid  = threadIdx.x;
    const int lane = tid & 31;
    const int wid  = tid >> 5;
    const int wq   = wid * 16;
    const int r8   = lane >> 2;
    const int la3  = lane & 3;
    const int bh   = blockIdx.y;
    const int qt   = blockIdx.x;

    const float* Q = g_q + (size_t)bh * S_ * HD + (size_t)qt * 128 * HD;
    const float* K = g_k + (size_t)bh * S_ * HD;
    const float* V = g_v + (size_t)bh * S_ * HD;

    // Stage Q (scaled, tf32, interleaved)
    {
        const int r  = tid >> 1;
        const int c0 = (tid & 1) * 32;
        #pragma unroll
        for (int jj = 0; jj < 4; jj++) {
            const int cc = c0 + jj * 8;
            float4 lo = *(const float4*)&Q[r * HD + cc];
            float4 hi = *(const float4*)&Q[r * HD + cc + 4];
            uint32_t* dst = &sQP[r * AP + cc];
            *(uint2*)(dst + 0) = make_uint2(f2tf(lo.x * 0.125f), f2tf(hi.x * 0.125f));
            *(uint2*)(dst + 2) = make_uint2(f2tf(lo.y * 0.125f), f2tf(hi.y * 0.125f));
            *(uint2*)(dst + 4) = make_uint2(f2tf(lo.z * 0.125f), f2tf(hi.z * 0.125f));
            *(uint2*)(dst + 6) = make_uint2(f2tf(lo.w * 0.125f), f2tf(hi.w * 0.125f));
        }
    }
    __syncthreads();

    // Hoist Q fragments (loop-invariant over kv)
    uint2 Qf0[8], Qf1[8];
    #pragma unroll
    for (int g = 0; g < 8; g++) {
        Qf0[g] = *(const uint2*)&sQP[(wq + r8) * AP + g * 8 + la3 * 2];
        Qf1[g] = *(const uint2*)&sQP[(wq + 8 + r8) * AP + g * 8 + la3 * 2];
    }

    float o[8][4];
    #pragma unroll
    for (int i = 0; i < 8; i++)
        #pragma unroll
        for (int j = 0; j < 4; j++) o[i][j] = 0.0f;
    float mr0 = -1e30f, mr1 = -1e30f;
    float lr0 = 0.0f,   lr1 = 0.0f;

    // per-thread constant interleave positions for P cols 2*la3, 2*la3+1
    const int pE0 = ((2 * la3) & 3) * 2 + ((2 * la3) >> 2);
    const int pE1 = ((2 * la3 + 1) & 3) * 2 + ((2 * la3 + 1) >> 2);

    for (int t = 0; t < 16; t++) {
        __syncthreads();   // all warps done with sK/sVt (and Qf loads at t=0)

        // Load K (interleaved) + V (transposed, kv-interleaved)
        {
            const int rr  = tid >> 2;          // 0..63
            const int c0  = (tid & 3) * 16;
            const int ipr = (rr >> 3) * 8 + (rr & 3) * 2 + ((rr >> 2) & 1);
            const float* Kt = K + (size_t)t * 64 * HD;
            const float* Vt = V + (size_t)t * 64 * HD;
            #pragma unroll
            for (int jj = 0; jj < 2; jj++) {
                const int cc = c0 + jj * 8;
                float4 lo = *(const float4*)&Kt[rr * HD + cc];
                float4 hi = *(const float4*)&Kt[rr * HD + cc + 4];
                uint32_t* dst = &sK[rr * AP + cc];
                *(uint2*)(dst + 0) = make_uint2(f2tf(lo.x), f2tf(hi.x));
                *(uint2*)(dst + 2) = make_uint2(f2tf(lo.y), f2tf(hi.y));
                *(uint2*)(dst + 4) = make_uint2(f2tf(lo.z), f2tf(hi.z));
                *(uint2*)(dst + 6) = make_uint2(f2tf(lo.w), f2tf(hi.w));
            }
            #pragma unroll
            for (int jj = 0; jj < 4; jj++) {
                const int cc = c0 + jj * 4;
                float4 v4 = *(const float4*)&Vt[rr * HD + cc];
                sVt[(cc + 0) * AP + ipr] = f2tf(v4.x);
                sVt[(cc + 1) * AP + ipr] = f2tf(v4.y);
                sVt[(cc + 2) * AP + ipr] = f2tf(v4.z);
                sVt[(cc + 3) * AP + ipr] = f2tf(v4.w);
            }
        }
        __syncthreads();

        // S = Q @ K^T (Q in registers)
        float s[8][4];
        #pragma unroll
        for (int i = 0; i < 8; i++)
            #pragma unroll
            for (int j = 0; j < 4; j++) s[i][j] = 0.0f;

        #pragma unroll
        for (int g = 0; g < 8; g++) {
            #pragma unroll
            for (int ni = 0; ni < 8; ni++) {
                uint2 b = *(const uint2*)&sK[(ni * 8 + r8) * AP + g * 8 + la3 * 2];
                mma_tf32(s[ni], Qf0[g].x, Qf1[g].x, Qf0[g].y, Qf1[g].y, b.x, b.y);
            }
        }

        // Online softmax (rows r8, r8+8 within warp; reduce over la3 quads)
        {
            float rm0 = -1e30f, rm1 = -1e30f;
            #pragma unroll
            for (int ni = 0; ni < 8; ni++) {
                rm0 = fmaxf(rm0, fmaxf(s[ni][0], s[ni][1]));
                rm1 = fmaxf(rm1, fmaxf(s[ni][2], s[ni][3]));
            }
            rm0 = fmaxf(rm0, __shfl_xor_sync(0xffffffffu, rm0, 1));
            rm0 = fmaxf(rm0, __shfl_xor_sync(0xffffffffu, rm0, 2));
            rm1 = fmaxf(rm1, __shfl_xor_sync(0xffffffffu, rm1, 1));
            rm1 = fmaxf(rm1, __shfl_xor_sync(0xffffffffu, rm1, 2));

            const float mn0 = fmaxf(mr0, rm0);
            const float mn1 = fmaxf(mr1, rm1);
            const float cor0 = __expf(mr0 - mn0);
            const float cor1 = __expf(mr1 - mn1);
            mr0 = mn0; mr1 = mn1;

            float rs0 = 0.0f, rs1 = 0.0f;
            #pragma unroll
            for (int ni = 0; ni < 8; ni++) {
                s[ni][0] = __expf(s[ni][0] - mn0);
                s[ni][1] = __expf(s[ni][1] - mn0);
                s[ni][2] = __expf(s[ni][2] - mn1);
                s[ni][3] = __expf(s[ni][3] - mn1);
                rs0 += s[ni][0] + s[ni][1];
                rs1 += s[ni][2] + s[ni][3];
            }
            rs0 += __shfl_xor_sync(0xffffffffu, rs0, 1);
            rs0 += __shfl_xor_sync(0xffffffffu, rs0, 2);
            rs1 += __shfl_xor_sync(0xffffffffu, rs1, 1);
            rs1 += __shfl_xor_sync(0xffffffffu, rs1, 2);
            lr0 = lr0 * cor0 + rs0;
            lr1 = lr1 * cor1 + rs1;

            #pragma unroll
            for (int ni = 0; ni < 8; ni++) {
                o[ni][0] *= cor0; o[ni][1] *= cor0;
                o[ni][2] *= cor1; o[ni][3] *= cor1;
            }
        }

        // P -> sQP (interleaved); rows warp-private
        {
            const int row0 = wq + r8;
            #pragma unroll
            for (int ni = 0; ni < 8; ni++) {
                uint32_t* b0p = &sQP[row0 * AP + ni * 8];
                uint32_t* b1p = &sQP[(row0 + 8) * AP + ni * 8];
                b0p[pE0] = f2tf(s[ni][0]);
                b0p[pE1] = f2tf(s[ni][1]);
                b1p[pE0] = f2tf(s[ni][2]);
                b1p[pE1] = f2tf(s[ni][3]);
            }
        }
        __syncwarp();

        // O += P @ V
        #pragma unroll
        for (int g = 0; g < 8; g++) {
            uint2 a0 = *(const uint2*)&sQP[(wq + r8) * AP + g * 8 + la3 * 2];
            uint2 a1 = *(const uint2*)&sQP[(wq + 8 + r8) * AP + g * 8 + la3 * 2];
            #pragma unroll
            for (int ni = 0; ni < 8; ni++) {
                uint2 b = *(const uint2*)&sVt[(ni * 8 + r8) * AP + g * 8 + la3 * 2];
                mma_tf32(o[ni], a0.x, a1.x, a0.y, a1.y, b.x, b.y);
            }
        }
    }

    // Epilogue: normalize, write [B, S, H]
    const int b = bh >> 4;
    const int h = bh & 15;
    const float inv0 = 1.0f / lr0;
    const float inv1 = 1.0f / lr1;
    const int s0 = qt * 128 + wq + r8;
    float* out0 = out + ((size_t)(b * S_ + s0)) * H_ + h * HD;
    float* out1 = out + ((size_t)(b * S_ + s0 + 8)) * H_ + h * HD;
    #pragma unroll
    for (int ni = 0; ni < 8; ni++) {
        const int dd = ni * 8 + la3 * 2;
        float2 v0 = {o[ni][0] * inv0, o[ni][1] * inv0};
        float2 v1 = {o[ni][2] * inv1, o[ni][3] * inv1};
        *(float2*)(out0 + dd) = v0;
        *(float2*)(out1 + dd) = v1;
    }
}

extern "C" void kernel_launch(void* const* d_in, const int* in_sizes, int n_in,
                              void* d_out, int out_size)
{
    const float* X  = (const float*)d_in[0];
    const float* Wq = (const float*)d_in[1];
    const float* Bq = (const float*)d_in[2];
    const float* Wk = (const float*)d_in[3];
    const float* Bk = (const float*)d_in[4];
    const float* Wv = (const float*)d_in[5];
    const float* Bv = (const float*)d_in[6];
    float* out = (float*)d_out;

    dim3 g1(H_ / 128, M_ / 128, 3);     // (8, 64, 3)
    qkv_gemm_tf32<<<g1, 256>>>(X, Wq, Bq, Wk, Bk, Wv, Bv);

    const int smem_attn = (128 + 64 + 64) * AP * 4;   // 73728 B
    cudaFuncSetAttribute(attn_tf32, cudaFuncAttributeMaxDynamicSharedMemorySize, smem_attn);
    dim3 g2(S_ / 128, B_ * NH);         // (8, 128)
    attn_tf32<<<g2, 256, smem_attn>>>(out);
}

// round 9
// speedup vs baseline: 2.7482x; 1.0469x over previous
#include <cuda_runtime.h>
#include <cstdint>

#define B_  8
#define S_  1024
#define H_  1024
#define NH  16
#define HD  64
#define M_  (B_ * S_)   // 8192

__device__ float g_q[B_ * NH * S_ * HD];
__device__ float g_k[B_ * NH * S_ * HD];
__device__ float g_v[B_ * NH * S_ * HD];

__device__ __forceinline__ uint32_t f2tf(float x) {
    uint32_t r;
    asm("cvt.rna.tf32.f32 %0, %1;" : "=r"(r) : "f"(x));
    return r;
}

__device__ __forceinline__ void mma_tf32(float c[4],
                                         uint32_t a0, uint32_t a1, uint32_t a2, uint32_t a3,
                                         uint32_t b0, uint32_t b1) {
    asm volatile(
        "mma.sync.aligned.m16n8k8.row.col.f32.tf32.tf32.f32 "
        "{%0,%1,%2,%3}, {%4,%5,%6,%7}, {%8,%9}, {%0,%1,%2,%3};\n"
        : "+f"(c[0]), "+f"(c[1]), "+f"(c[2]), "+f"(c[3])
        : "r"(a0), "r"(a1), "r"(a2), "r"(a3), "r"(b0), "r"(b1));
}

// ---------------------------------------------------------------------------
// TF32 QKV GEMM, k-pair interleaved smem (unchanged from R4 measured version).
// ---------------------------------------------------------------------------
#define GP 24

__global__ __launch_bounds__(256) void qkv_gemm_tf32(
    const float* __restrict__ X,
    const float* __restrict__ Wq, const float* __restrict__ Bq,
    const float* __restrict__ Wk, const float* __restrict__ Bk,
    const float* __restrict__ Wv, const float* __restrict__ Bv)
{
    const int which = blockIdx.z;
    const float* W    = (which == 0) ? Wq : (which == 1 ? Wk : Wv);
    const float* bias = (which == 0) ? Bq : (which == 1 ? Bk : Bv);
    float* out        = (which == 0) ? g_q : (which == 1 ? g_k : g_v);

    __shared__ uint32_t sA[2][128 * GP];
    __shared__ uint32_t sB[2][128 * GP];

    const int tid  = threadIdx.x;
    const int lane = tid & 31;
    const int wid  = tid >> 5;
    const int wm   = (wid >> 1) * 32;
    const int wn   = (wid & 1) * 64;
    const int m0   = blockIdx.y * 128;
    const int n0   = blockIdx.x * 128;
    const int r8   = lane >> 2;
    const int la3  = lane & 3;

    const int lrow = tid >> 1;
    const int lcol = (tid & 1) * 8;

    const float* pA = X + (size_t)(m0 + lrow) * H_ + lcol;
    const float* pB = W + (size_t)(n0 + lrow) * H_ + lcol;
    uint32_t* stA = &sA[0][0] + lrow * GP + lcol;
    uint32_t* stB = &sB[0][0] + lrow * GP + lcol;

    float c[2][8][4];
    #pragma unroll
    for (int i = 0; i < 2; i++)
        #pragma unroll
        for (int j = 0; j < 8; j++)
            #pragma unroll
            for (int k = 0; k < 4; k++) c[i][j][k] = 0.0f;

    float4 alo = *(const float4*)(pA);
    float4 ahi = *(const float4*)(pA + 4);
    float4 blo = *(const float4*)(pB);
    float4 bhi = *(const float4*)(pB + 4);
    {
        *(uint2*)(stA + 0) = make_uint2(f2tf(alo.x), f2tf(ahi.x));
        *(uint2*)(stA + 2) = make_uint2(f2tf(alo.y), f2tf(ahi.y));
        *(uint2*)(stA + 4) = make_uint2(f2tf(alo.z), f2tf(ahi.z));
        *(uint2*)(stA + 6) = make_uint2(f2tf(alo.w), f2tf(ahi.w));
        *(uint2*)(stB + 0) = make_uint2(f2tf(blo.x), f2tf(bhi.x));
        *(uint2*)(stB + 2) = make_uint2(f2tf(blo.y), f2tf(bhi.y));
        *(uint2*)(stB + 4) = make_uint2(f2tf(blo.z), f2tf(bhi.z));
        *(uint2*)(stB + 6) = make_uint2(f2tf(blo.w), f2tf(bhi.w));
    }
    __syncthreads();

    const int NT = H_ / 16;
    for (int t = 0; t < NT; t++) {
        const int cur = t & 1;
        if (t + 1 < NT) {
            const float* nA = pA + (t + 1) * 16;
            const float* nB = pB + (t + 1) * 16;
            alo = *(const float4*)(nA);
            ahi = *(const float4*)(nA + 4);
            blo = *(const float4*)(nB);
            bhi = *(const float4*)(nB + 4);
        }

        const uint32_t* cA = &sA[cur][0];
        const uint32_t* cB = &sB[cur][0];
        #pragma unroll
        for (int g = 0; g < 2; g++) {
            uint2 uA0[2], uA1[2];
            #pragma unroll
            for (int mi = 0; mi < 2; mi++) {
                uA0[mi] = *(const uint2*)&cA[(wm + mi * 16 + r8) * GP + g * 8 + la3 * 2];
                uA1[mi] = *(const uint2*)&cA[(wm + mi * 16 + 8 + r8) * GP + g * 8 + la3 * 2];
            }
            #pragma unroll
            for (int ni = 0; ni < 8; ni++) {
                uint2 uB = *(const uint2*)&cB[(wn + ni * 8 + r8) * GP + g * 8 + la3 * 2];
                #pragma unroll
                for (int mi = 0; mi < 2; mi++)
                    mma_tf32(c[mi][ni], uA0[mi].x, uA1[mi].x, uA0[mi].y, uA1[mi].y,
                             uB.x, uB.y);
            }
        }

        if (t + 1 < NT) {
            uint32_t* dA = stA + ((t + 1) & 1) * 128 * GP;
            uint32_t* dB = stB + ((t + 1) & 1) * 128 * GP;
            *(uint2*)(dA + 0) = make_uint2(f2tf(alo.x), f2tf(ahi.x));
            *(uint2*)(dA + 2) = make_uint2(f2tf(alo.y), f2tf(ahi.y));
            *(uint2*)(dA + 4) = make_uint2(f2tf(alo.z), f2tf(ahi.z));
            *(uint2*)(dA + 6) = make_uint2(f2tf(alo.w), f2tf(ahi.w));
            *(uint2*)(dB + 0) = make_uint2(f2tf(blo.x), f2tf(bhi.x));
            *(uint2*)(dB + 2) = make_uint2(f2tf(blo.y), f2tf(bhi.y));
            *(uint2*)(dB + 4) = make_uint2(f2tf(blo.z), f2tf(bhi.z));
            *(uint2*)(dB + 6) = make_uint2(f2tf(blo.w), f2tf(bhi.w));
        }
        __syncthreads();
    }

    #pragma unroll
    for (int mi = 0; mi < 2; mi++) {
        #pragma unroll
        for (int rh = 0; rh < 2; rh++) {
            const int m = m0 + wm + mi * 16 + r8 + rh * 8;
            const int b = m >> 10;
            const int s = m & 1023;
            float* orow = out + ((size_t)(b * NH) * S_ + s) * HD;
            #pragma unroll
            for (int ni = 0; ni < 8; ni++) {
                const int n = n0 + wn + ni * 8 + la3 * 2;
                const int h = n >> 6;
                const int dd = n & 63;
                float2 v;
                v.x = c[mi][ni][rh * 2 + 0] + bias[n];
                v.y = c[mi][ni][rh * 2 + 1] + bias[n + 1];
                *(float2*)(orow + (size_t)h * S_ * HD + dd) = v;
            }
        }
    }
}

// ---------------------------------------------------------------------------
// TF32 flash attention, P-DIRECT: S accumulators feed PV mma directly
// (a0=c0, a1=c2, a2=c1, a3=c3); V rows permuted within each kv 8-group by
// f^-1 so contraction indices line up. No P smem round trip, no syncwarp.
// smem: sQP[128] (Q staging only), sK[64], sVt[64] rows of AP=72 words.
// ---------------------------------------------------------------------------
#define AP 72

__global__ __launch_bounds__(256, 2) void attn_tf32(float* __restrict__ out)
{
    extern __shared__ uint32_t sm[];
    uint32_t* sQP = sm;                       // Q staging [128][AP]
    uint32_t* sK  = sQP + 128 * AP;           // [64][AP] (kv, d-interleaved)
    uint32_t* sVt = sK + 64 * AP;             // [64][AP] (d, kv-perm-interleaved)

    const int tid  = threadIdx.x;
    const int lane = tid & 31;
    const int wid  = tid >> 5;
    const int wq   = wid * 16;
    const int r8   = lane >> 2;
    const int la3  = lane & 3;
    const int bh   = blockIdx.y;
    const int qt   = blockIdx.x;

    const float* Q = g_q + (size_t)bh * S_ * HD + (size_t)qt * 128 * HD;
    const float* K = g_k + (size_t)bh * S_ * HD;
    const float* V = g_v + (size_t)bh * S_ * HD;

    // Stage Q (scaled, tf32, interleaved)
    {
        const int r  = tid >> 1;
        const int c0 = (tid & 1) * 32;
        #pragma unroll
        for (int jj = 0; jj < 4; jj++) {
            const int cc = c0 + jj * 8;
            float4 lo = *(const float4*)&Q[r * HD + cc];
            float4 hi = *(const float4*)&Q[r * HD + cc + 4];
            uint32_t* dst = &sQP[r * AP + cc];
            *(uint2*)(dst + 0) = make_uint2(f2tf(lo.x * 0.125f), f2tf(hi.x * 0.125f));
            *(uint2*)(dst + 2) = make_uint2(f2tf(lo.y * 0.125f), f2tf(hi.y * 0.125f));
            *(uint2*)(dst + 4) = make_uint2(f2tf(lo.z * 0.125f), f2tf(hi.z * 0.125f));
            *(uint2*)(dst + 6) = make_uint2(f2tf(lo.w * 0.125f), f2tf(hi.w * 0.125f));
        }
    }
    __syncthreads();

    // Hoist Q fragments (loop-invariant over kv)
    uint2 Qf0[8], Qf1[8];
    #pragma unroll
    for (int g = 0; g < 8; g++) {
        Qf0[g] = *(const uint2*)&sQP[(wq + r8) * AP + g * 8 + la3 * 2];
        Qf1[g] = *(const uint2*)&sQP[(wq + 8 + r8) * AP + g * 8 + la3 * 2];
    }

    float o[8][4];
    #pragma unroll
    for (int i = 0; i < 8; i++)
        #pragma unroll
        for (int j = 0; j < 4; j++) o[i][j] = 0.0f;
    float mr0 = -1e30f, mr1 = -1e30f;
    float lr0 = 0.0f,   lr1 = 0.0f;

    for (int t = 0; t < 16; t++) {
        __syncthreads();   // all warps done with sK/sVt (and Qf loads at t=0)

        // Load K (interleaved) + V (transposed, kv-PERMUTED-interleaved):
        // kv row rr stored at group (rr>>3), position ((rr>>1)&3)*2 + (rr&1)
        // so the PV B-fragment at logical slot k_l holds V[f(k_l)] matching
        // the P values the S accumulators hold at that slot.
        {
            const int rr  = tid >> 2;          // 0..63
            const int c0  = (tid & 3) * 16;
            const int ipr = (rr >> 3) * 8 + ((rr >> 1) & 3) * 2 + (rr & 1);
            const float* Kt = K + (size_t)t * 64 * HD;
            const float* Vt = V + (size_t)t * 64 * HD;
            #pragma unroll
            for (int jj = 0; jj < 2; jj++) {
                const int cc = c0 + jj * 8;
                float4 lo = *(const float4*)&Kt[rr * HD + cc];
                float4 hi = *(const float4*)&Kt[rr * HD + cc + 4];
                uint32_t* dst = &sK[rr * AP + cc];
                *(uint2*)(dst + 0) = make_uint2(f2tf(lo.x), f2tf(hi.x));
                *(uint2*)(dst + 2) = make_uint2(f2tf(lo.y), f2tf(hi.y));
                *(uint2*)(dst + 4) = make_uint2(f2tf(lo.z), f2tf(hi.z));
                *(uint2*)(dst + 6) = make_uint2(f2tf(lo.w), f2tf(hi.w));
            }
            #pragma unroll
            for (int jj = 0; jj < 4; jj++) {
                const int cc = c0 + jj * 4;
                float4 v4 = *(const float4*)&Vt[rr * HD + cc];
                sVt[(cc + 0) * AP + ipr] = f2tf(v4.x);
                sVt[(cc + 1) * AP + ipr] = f2tf(v4.y);
                sVt[(cc + 2) * AP + ipr] = f2tf(v4.z);
                sVt[(cc + 3) * AP + ipr] = f2tf(v4.w);
            }
        }
        __syncthreads();

        // S = Q @ K^T (Q in registers)
        float s[8][4];
        #pragma unroll
        for (int i = 0; i < 8; i++)
            #pragma unroll
            for (int j = 0; j < 4; j++) s[i][j] = 0.0f;

        #pragma unroll
        for (int g = 0; g < 8; g++) {
            #pragma unroll
            for (int ni = 0; ni < 8; ni++) {
                uint2 b = *(const uint2*)&sK[(ni * 8 + r8) * AP + g * 8 + la3 * 2];
                mma_tf32(s[ni], Qf0[g].x, Qf1[g].x, Qf0[g].y, Qf1[g].y, b.x, b.y);
            }
        }

        // Online softmax (rows r8, r8+8 within warp; reduce over la3 quads)
        {
            float rm0 = -1e30f, rm1 = -1e30f;
            #pragma unroll
            for (int ni = 0; ni < 8; ni++) {
                rm0 = fmaxf(rm0, fmaxf(s[ni][0], s[ni][1]));
                rm1 = fmaxf(rm1, fmaxf(s[ni][2], s[ni][3]));
            }
            rm0 = fmaxf(rm0, __shfl_xor_sync(0xffffffffu, rm0, 1));
            rm0 = fmaxf(rm0, __shfl_xor_sync(0xffffffffu, rm0, 2));
            rm1 = fmaxf(rm1, __shfl_xor_sync(0xffffffffu, rm1, 1));
            rm1 = fmaxf(rm1, __shfl_xor_sync(0xffffffffu, rm1, 2));

            const float mn0 = fmaxf(mr0, rm0);
            const float mn1 = fmaxf(mr1, rm1);
            const float cor0 = __expf(mr0 - mn0);
            const float cor1 = __expf(mr1 - mn1);
            mr0 = mn0; mr1 = mn1;

            float rs0 = 0.0f, rs1 = 0.0f;
            #pragma unroll
            for (int ni = 0; ni < 8; ni++) {
                s[ni][0] = __expf(s[ni][0] - mn0);
                s[ni][1] = __expf(s[ni][1] - mn0);
                s[ni][2] = __expf(s[ni][2] - mn1);
                s[ni][3] = __expf(s[ni][3] - mn1);
                rs0 += s[ni][0] + s[ni][1];
                rs1 += s[ni][2] + s[ni][3];
            }
            rs0 += __shfl_xor_sync(0xffffffffu, rs0, 1);
            rs0 += __shfl_xor_sync(0xffffffffu, rs0, 2);
            rs1 += __shfl_xor_sync(0xffffffffu, rs1, 1);
            rs1 += __shfl_xor_sync(0xffffffffu, rs1, 2);
            lr0 = lr0 * cor0 + rs0;
            lr1 = lr1 * cor1 + rs1;

            #pragma unroll
            for (int ni = 0; ni < 8; ni++) {
                o[ni][0] *= cor0; o[ni][1] *= cor0;
                o[ni][2] *= cor1; o[ni][3] *= cor1;
            }
        }

        // O += P @ V — P consumed DIRECTLY from S accumulators:
        // A-frag of kv-group g = S tile ni=g: a0=c0, a1=c2, a2=c1, a3=c3.
        #pragma unroll
        for (int g = 0; g < 8; g++) {
            const uint32_t pa0 = f2tf(s[g][0]);
            const uint32_t pa1 = f2tf(s[g][2]);
            const uint32_t pa2 = f2tf(s[g][1]);
            const uint32_t pa3 = f2tf(s[g][3]);
            #pragma unroll
            for (int ni = 0; ni < 8; ni++) {
                uint2 b = *(const uint2*)&sVt[(ni * 8 + r8) * AP + g * 8 + la3 * 2];
                mma_tf32(o[ni], pa0, pa1, pa2, pa3, b.x, b.y);
            }
        }
    }

    // Epilogue: normalize, write [B, S, H]
    const int b = bh >> 4;
    const int h = bh & 15;
    const float inv0 = 1.0f / lr0;
    const float inv1 = 1.0f / lr1;
    const int s0 = qt * 128 + wq + r8;
    float* out0 = out + ((size_t)(b * S_ + s0)) * H_ + h * HD;
    float* out1 = out + ((size_t)(b * S_ + s0 + 8)) * H_ + h * HD;
    #pragma unroll
    for (int ni = 0; ni < 8; ni++) {
        const int dd = ni * 8 + la3 * 2;
        float2 v0 = {o[ni][0] * inv0, o[ni][1] * inv0};
        float2 v1 = {o[ni][2] * inv1, o[ni][3] * inv1};
        *(float2*)(out0 + dd) = v0;
        *(float2*)(out1 + dd) = v1;
    }
}

extern "C" void kernel_launch(void* const* d_in, const int* in_sizes, int n_in,
                              void* d_out, int out_size)
{
    const float* X  = (const float*)d_in[0];
    const float* Wq = (const float*)d_in[1];
    const float* Bq = (const float*)d_in[2];
    const float* Wk = (const float*)d_in[3];
    const float* Bk = (const float*)d_in[4];
    const float* Wv = (const float*)d_in[5];
    const float* Bv = (const float*)d_in[6];
    float* out = (float*)d_out;

    dim3 g1(H_ / 128, M_ / 128, 3);     // (8, 64, 3)
    qkv_gemm_tf32<<<g1, 256>>>(X, Wq, Bq, Wk, Bk, Wv, Bv);

    const int smem_attn = (128 + 64 + 64) * AP * 4;   // 73728 B
    cudaFuncSetAttribute(attn_tf32, cudaFuncAttributeMaxDynamicSharedMemorySize, smem_attn);
    dim3 g2(S_ / 128, B_ * NH);         // (8, 128)
    attn_tf32<<<g2, 256, smem_attn>>>(out);
}